// round 14
// baseline (speedup 1.0000x reference)
#include <cuda_runtime.h>
#include <math.h>

#define NNODES 20000
#define CDIM   128
#define HHEADS 8
#define EEDGES 400000
#define BGRAPH 32
#define NP1    20001

// ------------------------- scratch -------------------------
__device__ float  g_xs [2*NNODES*CDIM];
__device__ float  g_h  [2*NNODES*CDIM];
__device__ float  g_als[4*NNODES*HHEADS];
__device__ float  g_ald[4*NNODES*HHEADS];
__device__ float  g_out[4*NNODES*CDIM];      // aggregated messages, ALREADY relu'd
__device__ double g_colsumd[4*CDIM];
__device__ double g_attnd[4];
__device__ float  g_feat[BGRAPH*512];
__device__ double g_featd[BGRAPH*512];
__device__ float  g_t1  [BGRAPH*128];
__device__ float  g_t2  [BGRAPH*64];
// CSR by destination (rows sorted by ORIGINAL edge index)
__device__ int    g_deg   [4*NNODES];
__device__ int    g_cur   [4*NNODES];
__device__ int    g_rowptr[4*NP1];
__device__ int    g_eidx  [4*EEDGES];        // edge indices per row (sorted)
__device__ int    g_esrc  [4*EEDGES];        // src per row slot (edge-order)

__constant__ int c_st[4] = {0,0,1,1};
__constant__ int c_dt[4] = {0,1,0,1};

__device__ __forceinline__ float negInf() { return __int_as_float(0xff800000); }

// ------------------------- input copy -------------------------
__global__ void load_input_kernel(const float* __restrict__ xb, const float* __restrict__ xd){
    int idx = blockIdx.x*256 + threadIdx.x;
    const int n4 = NNODES*CDIM/4;
    if (idx < n4){
        ((float4*)g_xs)[idx]      = ((const float4*)xb)[idx];
        ((float4*)g_xs)[n4 + idx] = ((const float4*)xd)[idx];
    }
}

// ------------------------- CSR build (per launch) -------------------------
__global__ void csr_zero_kernel(){
    int idx = blockIdx.x*256 + threadIdx.x;
    if (idx < 4*NNODES){ g_deg[idx] = 0; g_cur[idx] = 0; }
}
__global__ void csr_count_kernel(const int* ei0, const int* ei1, const int* ei2, const int* ei3){
    int e = blockIdx.y;
    const int* ei = (e==0)?ei0:(e==1)?ei1:(e==2)?ei2:ei3;
    int i = blockIdx.x*256 + threadIdx.x;
    if (i < EEDGES) atomicAdd(&g_deg[e*NNODES + ei[EEDGES + i]], 1);
}
__global__ void csr_scan_kernel(){      // 4 blocks, 1024 threads
    int e = blockIdx.x;
    __shared__ int ssum[1024];
    int t = threadIdx.x;
    int base = t*20;
    int local = 0;
    if (base < NNODES)
        for (int j=0;j<20;j++) local += g_deg[e*NNODES + base + j];
    ssum[t] = local;
    __syncthreads();
    for (int off=1; off<1024; off<<=1){
        int v = (t >= off) ? ssum[t-off] : 0;
        __syncthreads();
        ssum[t] += v;
        __syncthreads();
    }
    int run = ssum[t] - local;
    if (base < NNODES){
        for (int j=0;j<20;j++){
            g_rowptr[e*NP1 + base + j] = run;
            run += g_deg[e*NNODES + base + j];
        }
    }
    if (t == 0) g_rowptr[e*NP1 + NNODES] = EEDGES;
}
__global__ void csr_scatter_kernel(const int* ei0, const int* ei1, const int* ei2, const int* ei3){
    int e = blockIdx.y;
    const int* ei = (e==0)?ei0:(e==1)?ei1:(e==2)?ei2:ei3;
    int i = blockIdx.x*256 + threadIdx.x;
    if (i >= EEDGES) return;
    int d = ei[EEDGES + i];
    int pos = g_rowptr[e*NP1 + d] + atomicAdd(&g_cur[e*NNODES + d], 1);
    g_eidx[e*EEDGES + pos] = i;
}
// sort each row ascending by edge index (insertion sort; deg ~ 20), fill src
__global__ void row_sort_kernel(const int* ei0, const int* ei1, const int* ei2, const int* ei3){
    int e = blockIdx.y;
    const int* ei = (e==0)?ei0:(e==1)?ei1:(e==2)?ei2:ei3;
    int d = blockIdx.x*256 + threadIdx.x;
    if (d >= NNODES) return;
    int beg = g_rowptr[e*NP1 + d];
    int end = g_rowptr[e*NP1 + d + 1];
    int* row = g_eidx + (size_t)e*EEDGES;
    for (int p=beg+1; p<end; p++){
        int key = row[p];
        int q = p-1;
        while (q >= beg && row[q] > key){ row[q+1] = row[q]; q--; }
        row[q+1] = key;
    }
    int* srow = g_esrc + (size_t)e*EEDGES;
    for (int p=beg; p<end; p++) srow[p] = ei[row[p]];
}

__global__ void colsum_zero_kernel(){ g_colsumd[threadIdx.x] = 0.0; }   // 512 threads

// ---- GEMM [N,128]@[128,128]: plain fp32 FMA ----
// sel==0: g_h[y] = g_xs[y]@W + b ; sel==1: colsumd[y] += sum_n tanhf(g_out[y]@W + b)
__global__ void __launch_bounds__(256)
gemm128_kernel(const float* __restrict__ W0, int strideW,
               const float* __restrict__ b0, int strideB, int sel)
{
    __shared__ float As[32][132];
    __shared__ float Ws[32][128];
    __shared__ float red[16][128];

    const int y = blockIdx.y;
    const float* A    = (sel == 0 ? g_xs : g_out) + (size_t)y*NNODES*CDIM;
    const float* W    = W0 + (size_t)y*strideW;
    const float* bias = b0 + (size_t)y*strideB;

    int row0 = blockIdx.x * 128;
    int t  = threadIdx.x;
    int tx = t & 15, ty = t >> 4;

    float acc[8][8];
#pragma unroll
    for (int i=0;i<8;i++)
#pragma unroll
        for (int j=0;j<8;j++) acc[i][j] = 0.f;

    for (int kk=0; kk<128; kk+=32){
#pragma unroll
        for (int i=0;i<16;i++){
            int idx = i*256 + t;
            int m = idx >> 5, k = idx & 31;
            int r = row0 + m;
            As[k][m] = (r < NNODES) ? A[(size_t)r*128 + kk + k] : 0.f;
        }
#pragma unroll
        for (int i=0;i<16;i++){
            int idx = i*256 + t;
            int k = idx >> 7, n = idx & 127;
            Ws[k][n] = W[(size_t)(kk+k)*128 + n];
        }
        __syncthreads();
#pragma unroll
        for (int k=0;k<32;k++){
            float4 a0 = *((const float4*)&As[k][ty*8]);
            float4 a1 = *((const float4*)&As[k][ty*8+4]);
            float4 b0v= *((const float4*)&Ws[k][tx*8]);
            float4 b1v= *((const float4*)&Ws[k][tx*8+4]);
            float a[8] = {a0.x,a0.y,a0.z,a0.w,a1.x,a1.y,a1.z,a1.w};
            float b[8] = {b0v.x,b0v.y,b0v.z,b0v.w,b1v.x,b1v.y,b1v.z,b1v.w};
#pragma unroll
            for (int i=0;i<8;i++)
#pragma unroll
                for (int j=0;j<8;j++) acc[i][j] = fmaf(a[i], b[j], acc[i][j]);
        }
        __syncthreads();
    }

    if (sel == 0){
        float* O = g_h + (size_t)y*NNODES*CDIM;
#pragma unroll
        for (int i=0;i<8;i++){
            int r = row0 + ty*8 + i;
            if (r < NNODES){
#pragma unroll
                for (int j=0;j<8;j++)
                    O[(size_t)r*128 + tx*8 + j] = __fadd_rn(acc[i][j], bias[tx*8+j]);
            }
        }
    } else {
        float part[8];
#pragma unroll
        for (int j=0;j<8;j++) part[j] = 0.f;
#pragma unroll
        for (int i=0;i<8;i++){
            int r = row0 + ty*8 + i;
            if (r < NNODES)
#pragma unroll
                for (int j=0;j<8;j++)
                    part[j] += tanhf(__fadd_rn(acc[i][j], bias[tx*8+j]));
        }
#pragma unroll
        for (int j=0;j<8;j++) red[ty][tx*8+j] = part[j];
        __syncthreads();
        if (t < 128){
            float s = 0.f;
#pragma unroll
            for (int g=0; g<16; g++) s += red[g][t];
            atomicAdd(&g_colsumd[y*CDIM + t], (double)s);
        }
    }
}

// ------------------ attention logits per node (mul then add, fp32) ------------------
__global__ void alin_kernel(const float* __restrict__ asrc_l, const float* __restrict__ adst_l){
    int e = blockIdx.y >> 1, side = blockIdx.y & 1;
    int type = side ? c_dt[e] : c_st[e];
    const float* av = (side ? adst_l : asrc_l) + e*128;

    __shared__ float avs[128];
    if (threadIdx.x < 128) avs[threadIdx.x] = av[threadIdx.x];
    __syncthreads();

    int t = threadIdx.x;
    int n = blockIdx.x*32 + (t >> 3);
    int h = t & 7;
    if (n >= NNODES) return;

    const float* hp = g_h + (size_t)type*NNODES*CDIM + (size_t)n*128 + h*16;
    float s = 0.f;
#pragma unroll
    for (int d=0; d<16; d++) s = __fadd_rn(s, __fmul_rn(hp[d], avs[h*16 + d]));
    float* outp = (side ? g_ald : g_als) + (size_t)e*NNODES*HHEADS;
    outp[n*8 + h] = s;
}

// ------------------ edge softmax+aggregate: warp per destination --------------------
// Rows sorted by edge index -> all serial fp32 sums replicate segment_sum in
// deterministic (edge-order) update order.
__global__ void __launch_bounds__(256)
dst_attn_kernel(){
    int e = blockIdx.y;
    int d = blockIdx.x*8 + (threadIdx.x >> 5);
    if (d >= NNODES) return;
    int lane = threadIdx.x & 31;
    int h = lane >> 2;

    const int* srcs = g_esrc + (size_t)e*EEDGES;
    int beg = g_rowptr[e*NP1 + d];
    int end = g_rowptr[e*NP1 + d + 1];

    const float* als = g_als + (size_t)e*NNODES*HHEADS;
    float ald = g_ald[(size_t)e*NNODES*HHEADS + d*8 + h];
    const float* hsrc = g_h + (size_t)c_st[e]*NNODES*CDIM;

    float m = negInf();
    for (int p=beg; p<end; p++){
        float sc = __fadd_rn(als[srcs[p]*8 + h], ald);
        sc = (sc >= 0.f) ? sc : __fmul_rn(0.2f, sc);
        m = fmaxf(m, sc);
    }
    float z = 0.f;
    for (int p=beg; p<end; p++){
        float sc = __fadd_rn(als[srcs[p]*8 + h], ald);
        sc = (sc >= 0.f) ? sc : __fmul_rn(0.2f, sc);
        z = __fadd_rn(z, expf(__fadd_rn(sc, -m)));
    }
    float4 acc = make_float4(0.f,0.f,0.f,0.f);
    for (int p=beg; p<end; p++){
        int s = srcs[p];
        float sc = __fadd_rn(als[s*8 + h], ald);
        sc = (sc >= 0.f) ? sc : __fmul_rn(0.2f, sc);
        float alpha = __fdiv_rn(expf(__fadd_rn(sc, -m)), z);
        float4 v = *((const float4*)(hsrc + (size_t)s*128) + lane);
        acc.x = __fadd_rn(acc.x, __fmul_rn(alpha, v.x));
        acc.y = __fadd_rn(acc.y, __fmul_rn(alpha, v.y));
        acc.z = __fadd_rn(acc.z, __fmul_rn(alpha, v.z));
        acc.w = __fadd_rn(acc.w, __fmul_rn(alpha, v.w));
    }
    float4 r;
    r.x = fmaxf(acc.x, 0.f); r.y = fmaxf(acc.y, 0.f);
    r.z = fmaxf(acc.z, 0.f); r.w = fmaxf(acc.w, 0.f);
    *((float4*)(g_out + (size_t)e*NNODES*CDIM + (size_t)d*128) + lane) = r;
}

// ------------------------- semantic attention (fp64 reduce) -------------------------
__global__ void semscore_kernel(const float* __restrict__ q_l){
    __shared__ double redbuf[128];
    __shared__ double sp[4];
    int t = threadIdx.x;   // 128
    double qv = (double)q_l[t];
    for (int p=0;p<4;p++){
        redbuf[t] = qv * g_colsumd[p*128 + t];
        __syncthreads();
        for (int s=64; s>0; s>>=1){
            if (t < s) redbuf[t] += redbuf[t+s];
            __syncthreads();
        }
        if (t == 0) sp[p] = redbuf[0] * (1.0/(double)NNODES);
        __syncthreads();
    }
    if (t == 0){
        double a0 = sp[0], a1 = sp[2];
        double mx = fmax(a0,a1);
        double e0 = exp(a0-mx), e1 = exp(a1-mx);
        g_attnd[0] = e0/(e0+e1); g_attnd[1] = e1/(e0+e1);
        a0 = sp[1]; a1 = sp[3];
        mx = fmax(a0,a1);
        e0 = exp(a0-mx); e1 = exp(a1-mx);
        g_attnd[2] = e0/(e0+e1); g_attnd[3] = e1/(e0+e1);
    }
}

// ------------------------- combine (g_out already relu'd) -------------------------
__global__ void combine_kernel(){
    int t = blockIdx.y;
    float a0 = (float)g_attnd[t*2], a1 = (float)g_attnd[t*2+1];
    int idx = blockIdx.x*256 + threadIdx.x;
    const int n4 = NNODES*CDIM/4;
    if (idx >= n4) return;
    int pa = (t==0) ? 0 : 1;
    int pb = (t==0) ? 2 : 3;
    float4 va = ((const float4*)(g_out + (size_t)pa*NNODES*CDIM))[idx];
    float4 vb = ((const float4*)(g_out + (size_t)pb*NNODES*CDIM))[idx];
    float4 r;
    r.x = fmaxf(__fadd_rn(__fmul_rn(a0,va.x), __fmul_rn(a1,vb.x)), 0.f);
    r.y = fmaxf(__fadd_rn(__fmul_rn(a0,va.y), __fmul_rn(a1,vb.y)), 0.f);
    r.z = fmaxf(__fadd_rn(__fmul_rn(a0,va.z), __fmul_rn(a1,vb.z)), 0.f);
    r.w = fmaxf(__fadd_rn(__fmul_rn(a0,va.w), __fmul_rn(a1,vb.w)), 0.f);
    ((float4*)(g_xs + (size_t)t*NNODES*CDIM))[idx] = r;
}

// ---------- pooling: serial fp32 in node order per (graph, column) ----------
// block = (b, t), 128 threads = columns; binary search on sorted batch array.
__global__ void pool_kernel(const int* __restrict__ b0, const int* __restrict__ b1){
    int b = blockIdx.x, t = blockIdx.y;
    const int* batch = t ? b1 : b0;
    int lo, hi;
    {
        int l=0, r=NNODES;
        while (l<r){ int m=(l+r)>>1; if (batch[m] < b) l=m+1; else r=m; }
        lo = l;
        l=0; r=NNODES;
        while (l<r){ int m=(l+r)>>1; if (batch[m] < b+1) l=m+1; else r=m; }
        hi = l;
    }
    int c = threadIdx.x;
    const float* x = g_xs + (size_t)t*NNODES*CDIM;
    float mx = negInf(), sm = 0.f;
    for (int n=lo; n<hi; n++){
        float v = x[(size_t)n*128 + c];
        mx = fmaxf(mx, v);
        sm = __fadd_rn(sm, v);
    }
    if (hi == lo) mx = 0.f;                       // empty-graph max -> 0
    int cnt = hi - lo;
    float mean = __fdiv_rn(sm, (float)(cnt > 0 ? cnt : 1));
    g_featd[b*512 + t*256 + c]        = (double)mx;
    g_featd[b*512 + t*256 + 128 + c]  = (double)mean;
}

// ------------------------- PairNorm (fp64) + MLP (fp32) ---------------------------
__global__ void pairnorm_kernel(){
    __shared__ double rss[BGRAPH];
    int c = threadIdx.x;   // 512 threads
    double col[BGRAPH];
    double s = 0.0;
#pragma unroll
    for (int b=0;b<BGRAPH;b++){ col[b] = g_featd[b*512 + c]; s += col[b]; }
    double mean = s * (1.0/(double)BGRAPH);
#pragma unroll
    for (int b=0;b<BGRAPH;b++){ col[b] -= mean; g_featd[b*512 + c] = col[b]; }
    __syncthreads();
    if (c < BGRAPH){
        double ss = 0.0;
        for (int k=0;k<512;k++){ double v = g_featd[c*512 + k]; ss += v*v; }
        rss[c] = 1.0 / sqrt(1e-6 + ss);
    }
    __syncthreads();
#pragma unroll
    for (int b=0;b<BGRAPH;b++) g_feat[b*512 + c] = (float)(100.0 * col[b] * rss[b]);
}

__global__ void mlp1_kernel(const float* __restrict__ w, const float* __restrict__ bias){
    __shared__ float f[512];
    int b = blockIdx.x, t = threadIdx.x;   // 128
    for (int i=t;i<512;i+=128) f[i] = g_feat[b*512 + i];
    __syncthreads();
    float acc = 0.f;
    for (int k=0;k<512;k++) acc = fmaf(f[k], w[k*128 + t], acc);
    g_t1[b*128 + t] = fmaxf(__fadd_rn(acc, bias[t]), 0.f);
}

__global__ void mlp2_kernel(const float* __restrict__ w, const float* __restrict__ bias){
    __shared__ float f[128];
    int b = blockIdx.x, t = threadIdx.x;   // 64
    f[t]    = g_t1[b*128 + t];
    f[t+64] = g_t1[b*128 + t + 64];
    __syncthreads();
    float acc = 0.f;
    for (int k=0;k<128;k++) acc = fmaf(f[k], w[k*64 + t], acc);
    g_t2[b*64 + t] = fmaxf(__fadd_rn(acc, bias[t]), 0.f);
}

__global__ void mlp3_kernel(const float* __restrict__ w, const float* __restrict__ bias,
                            float* __restrict__ out){
    int t = threadIdx.x;   // 64
    if (t >= 2*BGRAPH) return;
    int b = t >> 1, o = t & 1;
    float acc = 0.f;
    for (int k=0;k<64;k++) acc = fmaf(g_t2[b*64 + k], w[k*2 + o], acc);
    out[b*2 + o] = __fadd_rn(acc, bias[o]);
}

// ------------------------- host driver -------------------------
extern "C" void kernel_launch(void* const* d_in, const int* in_sizes, int n_in,
                              void* d_out, int out_size)
{
    const float* proj_w = (const float*)d_in[2];
    const float* proj_b = (const float*)d_in[3];
    const float* a_src  = (const float*)d_in[4];
    const float* a_dst  = (const float*)d_in[5];
    const float* k_w    = (const float*)d_in[6];
    const float* k_b    = (const float*)d_in[7];
    const float* qv     = (const float*)d_in[8];
    const int* ei_bb = (const int*)d_in[15];
    const int* ei_bd = (const int*)d_in[16];
    const int* ei_db = (const int*)d_in[17];
    const int* ei_dd = (const int*)d_in[18];
    const int* batch_b = (const int*)d_in[19];
    const int* batch_d = (const int*)d_in[20];
    float* out = (float*)d_out;

    const int gemmBlocks = (NNODES + 127) / 128;
    const int eBlocks    = (EEDGES + 255) / 256;
    const int dstBlocks  = (NNODES + 7) / 8;
    const int nBlocks256 = (NNODES + 255) / 256;
    const int n4Blocks   = (NNODES*CDIM/4 + 255) / 256;

    load_input_kernel<<<n4Blocks, 256>>>((const float*)d_in[0], (const float*)d_in[1]);

    // CSR build with edge-order rows
    csr_zero_kernel<<<(4*NNODES + 255)/256, 256>>>();
    csr_count_kernel<<<dim3(eBlocks,4), 256>>>(ei_bb, ei_bd, ei_db, ei_dd);
    csr_scan_kernel<<<4, 1024>>>();
    csr_scatter_kernel<<<dim3(eBlocks,4), 256>>>(ei_bb, ei_bd, ei_db, ei_dd);
    row_sort_kernel<<<dim3(nBlocks256,4), 256>>>(ei_bb, ei_bd, ei_db, ei_dd);

    for (int l=0; l<3; l++){
        colsum_zero_kernel<<<1, 512>>>();

        gemm128_kernel<<<dim3(gemmBlocks,2), 256>>>(
            proj_w + (size_t)l*2*CDIM*CDIM, CDIM*CDIM,
            proj_b + (size_t)l*2*CDIM,      CDIM, 0);

        alin_kernel<<<dim3((NNODES+31)/32, 8), 256>>>(
            a_src + (size_t)l*4*CDIM, a_dst + (size_t)l*4*CDIM);

        dst_attn_kernel<<<dim3(dstBlocks,4), 256>>>();

        gemm128_kernel<<<dim3(gemmBlocks,4), 256>>>(
            k_w + (size_t)l*CDIM*CDIM, 0,
            k_b + (size_t)l*CDIM,      0, 1);
        semscore_kernel<<<1, 128>>>(qv + (size_t)l*CDIM);

        combine_kernel<<<dim3(n4Blocks,2), 256>>>();
    }

    pool_kernel<<<dim3(BGRAPH,2), 128>>>(batch_b, batch_d);

    pairnorm_kernel<<<1, 512>>>();
    mlp1_kernel<<<BGRAPH, 128>>>((const float*)d_in[9],  (const float*)d_in[10]);
    mlp2_kernel<<<BGRAPH, 64>>>((const float*)d_in[11], (const float*)d_in[12]);
    mlp3_kernel<<<1, 64>>>((const float*)d_in[13], (const float*)d_in[14], out);

    (void)in_sizes; (void)n_in; (void)out_size;
}

// round 15
// speedup vs baseline: 1.3803x; 1.3803x over previous
#include <cuda_runtime.h>
#include <math.h>

#define NNODES 20000
#define CDIM   128
#define HHEADS 8
#define EEDGES 400000
#define BGRAPH 32
#define NP1    20001

typedef unsigned long long u64;

// ------------------------- scratch -------------------------
__device__ float  g_xs [2*NNODES*CDIM];
__device__ float  g_h  [2*NNODES*CDIM];
__device__ float  g_als[4*NNODES*HHEADS];
__device__ float  g_ald[4*NNODES*HHEADS];
__device__ float  g_out[4*NNODES*CDIM];      // aggregated messages, ALREADY relu'd
__device__ double g_colsumd[4*CDIM];
__device__ double g_attnd[4];
__device__ float  g_feat[BGRAPH*512];
__device__ double g_featd[BGRAPH*512];
__device__ float  g_t1  [BGRAPH*128];
__device__ float  g_t2  [BGRAPH*64];
// CSR by destination (rows sorted by ORIGINAL edge index)
__device__ int    g_deg   [4*NNODES];
__device__ int    g_cur   [4*NNODES];
__device__ int    g_rowptr[4*NP1];
__device__ int    g_eidx  [4*EEDGES];
__device__ int    g_esrc  [4*EEDGES];

__constant__ int c_st[4] = {0,0,1,1};
__constant__ int c_dt[4] = {0,1,0,1};
// alin combos per type: 4 (edge,side) pairs touching that node type
__constant__ int cmb_e [2][4] = {{0,1,0,2},{2,3,1,3}};
__constant__ int cmb_sd[2][4] = {{0,0,1,1},{0,0,1,1}};   // 0=src, 1=dst

__device__ __forceinline__ float negInf() { return __int_as_float(0xff800000); }

// packed f32x2 helpers (two independent IEEE fp32 FMAs -> bit-identical to scalar)
__device__ __forceinline__ u64 pack2(float lo, float hi){
    u64 r; asm("mov.b64 %0, {%1, %2};" : "=l"(r) : "f"(lo), "f"(hi)); return r;
}
__device__ __forceinline__ void fma2(u64& acc, u64 a, u64 b){
    asm("fma.rn.f32x2 %0, %1, %2, %0;" : "+l"(acc) : "l"(a), "l"(b));
}
__device__ __forceinline__ float2 unpack2(u64 v){
    float2 r; asm("mov.b64 {%0, %1}, %2;" : "=f"(r.x), "=f"(r.y) : "l"(v)); return r;
}

// ------------------------- input copy -------------------------
__global__ void load_input_kernel(const float* __restrict__ xb, const float* __restrict__ xd){
    int idx = blockIdx.x*256 + threadIdx.x;
    const int n4 = NNODES*CDIM/4;
    if (idx < n4){
        ((float4*)g_xs)[idx]      = ((const float4*)xb)[idx];
        ((float4*)g_xs)[n4 + idx] = ((const float4*)xd)[idx];
    }
}

// ------------------------- CSR build (per launch) -------------------------
__global__ void csr_zero_kernel(){
    int idx = blockIdx.x*256 + threadIdx.x;
    if (idx < 4*NNODES){ g_deg[idx] = 0; g_cur[idx] = 0; }
}
__global__ void csr_count_kernel(const int* ei0, const int* ei1, const int* ei2, const int* ei3){
    int e = blockIdx.y;
    const int* ei = (e==0)?ei0:(e==1)?ei1:(e==2)?ei2:ei3;
    int i = blockIdx.x*256 + threadIdx.x;
    if (i < EEDGES) atomicAdd(&g_deg[e*NNODES + ei[EEDGES + i]], 1);
}
__global__ void csr_scan_kernel(){      // 4 blocks, 1024 threads
    int e = blockIdx.x;
    __shared__ int ssum[1024];
    int t = threadIdx.x;
    int base = t*20;
    int local = 0;
    if (base < NNODES)
        for (int j=0;j<20;j++) local += g_deg[e*NNODES + base + j];
    ssum[t] = local;
    __syncthreads();
    for (int off=1; off<1024; off<<=1){
        int v = (t >= off) ? ssum[t-off] : 0;
        __syncthreads();
        ssum[t] += v;
        __syncthreads();
    }
    int run = ssum[t] - local;
    if (base < NNODES){
        for (int j=0;j<20;j++){
            g_rowptr[e*NP1 + base + j] = run;
            run += g_deg[e*NNODES + base + j];
        }
    }
    if (t == 0) g_rowptr[e*NP1 + NNODES] = EEDGES;
}
__global__ void csr_scatter_kernel(const int* ei0, const int* ei1, const int* ei2, const int* ei3){
    int e = blockIdx.y;
    const int* ei = (e==0)?ei0:(e==1)?ei1:(e==2)?ei2:ei3;
    int i = blockIdx.x*256 + threadIdx.x;
    if (i >= EEDGES) return;
    int d = ei[EEDGES + i];
    int pos = g_rowptr[e*NP1 + d] + atomicAdd(&g_cur[e*NNODES + d], 1);
    g_eidx[e*EEDGES + pos] = i;
}
__global__ void row_sort_kernel(const int* ei0, const int* ei1, const int* ei2, const int* ei3){
    int e = blockIdx.y;
    const int* ei = (e==0)?ei0:(e==1)?ei1:(e==2)?ei2:ei3;
    int d = blockIdx.x*256 + threadIdx.x;
    if (d >= NNODES) return;
    int beg = g_rowptr[e*NP1 + d];
    int end = g_rowptr[e*NP1 + d + 1];
    int* row = g_eidx + (size_t)e*EEDGES;
    for (int p=beg+1; p<end; p++){
        int key = row[p];
        int q = p-1;
        while (q >= beg && row[q] > key){ row[q+1] = row[q]; q--; }
        row[q+1] = key;
    }
    int* srow = g_esrc + (size_t)e*EEDGES;
    for (int p=beg; p<end; p++) srow[p] = ei[row[p]];
}

__global__ void colsum_zero_kernel(){ g_colsumd[threadIdx.x] = 0.0; }   // 512 threads

// ---- GEMM [N,128]@[128,128]: plain fp32, packed f32x2 FMA (bit-identical) ----
// sel==0: g_h[y] = g_xs[y]@W + b ; sel==1: colsumd[y] += sum_n tanhf(g_out[y]@W + b)
__global__ void __launch_bounds__(256)
gemm128_kernel(const float* __restrict__ W0, int strideW,
               const float* __restrict__ b0, int strideB, int sel)
{
    __shared__ float As[32][132];
    __shared__ float Ws[32][128];
    __shared__ float red[16][128];

    const int y = blockIdx.y;
    const float* A    = (sel == 0 ? g_xs : g_out) + (size_t)y*NNODES*CDIM;
    const float* W    = W0 + (size_t)y*strideW;
    const float* bias = b0 + (size_t)y*strideB;

    int row0 = blockIdx.x * 128;
    int t  = threadIdx.x;
    int tx = t & 15, ty = t >> 4;

    u64 acc2[8][4];
#pragma unroll
    for (int i=0;i<8;i++)
#pragma unroll
        for (int jp=0;jp<4;jp++) acc2[i][jp] = 0ULL;

    for (int kk=0; kk<128; kk+=32){
#pragma unroll
        for (int i=0;i<16;i++){
            int idx = i*256 + t;
            int m = idx >> 5, k = idx & 31;
            int r = row0 + m;
            As[k][m] = (r < NNODES) ? A[(size_t)r*128 + kk + k] : 0.f;
        }
#pragma unroll
        for (int i=0;i<16;i++){
            int idx = i*256 + t;
            int k = idx >> 7, n = idx & 127;
            Ws[k][n] = W[(size_t)(kk+k)*128 + n];
        }
        __syncthreads();
#pragma unroll
        for (int k=0;k<32;k++){
            float4 a0 = *((const float4*)&As[k][ty*8]);
            float4 a1 = *((const float4*)&As[k][ty*8+4]);
            float4 b0v= *((const float4*)&Ws[k][tx*8]);
            float4 b1v= *((const float4*)&Ws[k][tx*8+4]);
            u64 b2[4];
            b2[0] = pack2(b0v.x, b0v.y); b2[1] = pack2(b0v.z, b0v.w);
            b2[2] = pack2(b1v.x, b1v.y); b2[3] = pack2(b1v.z, b1v.w);
            float a[8] = {a0.x,a0.y,a0.z,a0.w,a1.x,a1.y,a1.z,a1.w};
#pragma unroll
            for (int i=0;i<8;i++){
                u64 ad = pack2(a[i], a[i]);
#pragma unroll
                for (int jp=0;jp<4;jp++) fma2(acc2[i][jp], ad, b2[jp]);
            }
        }
        __syncthreads();
    }

    if (sel == 0){
        float* O = g_h + (size_t)y*NNODES*CDIM;
#pragma unroll
        for (int i=0;i<8;i++){
            int r = row0 + ty*8 + i;
            if (r < NNODES){
#pragma unroll
                for (int jp=0;jp<4;jp++){
                    float2 v = unpack2(acc2[i][jp]);
                    O[(size_t)r*128 + tx*8 + jp*2]     = __fadd_rn(v.x, bias[tx*8+jp*2]);
                    O[(size_t)r*128 + tx*8 + jp*2 + 1] = __fadd_rn(v.y, bias[tx*8+jp*2+1]);
                }
            }
        }
    } else {
        float part[8];
#pragma unroll
        for (int j=0;j<8;j++) part[j] = 0.f;
#pragma unroll
        for (int i=0;i<8;i++){
            int r = row0 + ty*8 + i;
            if (r < NNODES){
#pragma unroll
                for (int jp=0;jp<4;jp++){
                    float2 v = unpack2(acc2[i][jp]);
                    part[jp*2]   += tanhf(__fadd_rn(v.x, bias[tx*8+jp*2]));
                    part[jp*2+1] += tanhf(__fadd_rn(v.y, bias[tx*8+jp*2+1]));
                }
            }
        }
#pragma unroll
        for (int j=0;j<8;j++) red[ty][tx*8+j] = part[j];
        __syncthreads();
        if (t < 128){
            float s = 0.f;
#pragma unroll
            for (int g=0; g<16; g++) s += red[g][t];
            atomicAdd(&g_colsumd[y*CDIM + t], (double)s);
        }
    }
}

// ---- attention logits: one g_h row read serves all 4 (edge,side) combos of a type --
__global__ void alin2_kernel(const float* __restrict__ asrc_l, const float* __restrict__ adst_l){
    int type = blockIdx.y;
    __shared__ float avs[4][128];
    for (int i=threadIdx.x; i<512; i+=256){
        int cc = i >> 7, dd = i & 127;
        const float* src = cmb_sd[type][cc] ? adst_l : asrc_l;
        avs[cc][dd] = src[cmb_e[type][cc]*128 + dd];
    }
    __syncthreads();

    int t = threadIdx.x;
    int n = blockIdx.x*32 + (t >> 3);
    int h = t & 7;
    if (n >= NNODES) return;

    const float* hp = g_h + (size_t)type*NNODES*CDIM + (size_t)n*128 + h*16;
    float hv[16];
#pragma unroll
    for (int d=0; d<16; d++) hv[d] = hp[d];

#pragma unroll
    for (int cc=0; cc<4; cc++){
        float s = 0.f;
#pragma unroll
        for (int d=0; d<16; d++) s = __fadd_rn(s, __fmul_rn(hv[d], avs[cc][h*16 + d]));
        int e = cmb_e[type][cc];
        float* outp = (cmb_sd[type][cc] ? g_ald : g_als) + (size_t)e*NNODES*HHEADS;
        outp[n*8 + h] = s;
    }
}

// ------------------ edge softmax+aggregate: warp per destination, 2 passes ----------
// Rows in edge-index order -> serial fp32 sums replicate segment_sum update order.
// Pass 2 fuses exp-sum (z) and unnormalized aggregation; divide by z once at the end.
__global__ void __launch_bounds__(256)
dst_attn_kernel(){
    int e = blockIdx.y;
    int d = blockIdx.x*8 + (threadIdx.x >> 5);
    if (d >= NNODES) return;
    int lane = threadIdx.x & 31;
    int h = lane >> 2;

    const int* srcs = g_esrc + (size_t)e*EEDGES;
    int beg = g_rowptr[e*NP1 + d];
    int end = g_rowptr[e*NP1 + d + 1];

    const float* als = g_als + (size_t)e*NNODES*HHEADS;
    float ald = g_ald[(size_t)e*NNODES*HHEADS + d*8 + h];
    const float* hsrc = g_h + (size_t)c_st[e]*NNODES*CDIM;

    float m = negInf();
    for (int p=beg; p<end; p++){
        float sc = __fadd_rn(als[srcs[p]*8 + h], ald);
        sc = (sc >= 0.f) ? sc : __fmul_rn(0.2f, sc);
        m = fmaxf(m, sc);
    }
    float z = 0.f;
    float4 acc = make_float4(0.f,0.f,0.f,0.f);
    for (int p=beg; p<end; p++){
        int s = srcs[p];
        float sc = __fadd_rn(als[s*8 + h], ald);
        sc = (sc >= 0.f) ? sc : __fmul_rn(0.2f, sc);
        float ex = expf(__fadd_rn(sc, -m));
        z = __fadd_rn(z, ex);
        float4 v = *((const float4*)(hsrc + (size_t)s*128) + lane);
        acc.x = __fadd_rn(acc.x, __fmul_rn(ex, v.x));
        acc.y = __fadd_rn(acc.y, __fmul_rn(ex, v.y));
        acc.z = __fadd_rn(acc.z, __fmul_rn(ex, v.z));
        acc.w = __fadd_rn(acc.w, __fmul_rn(ex, v.w));
    }
    float4 r;                  // relu also maps deg=0 NaN (0/0) to 0
    r.x = fmaxf(__fdiv_rn(acc.x, z), 0.f);
    r.y = fmaxf(__fdiv_rn(acc.y, z), 0.f);
    r.z = fmaxf(__fdiv_rn(acc.z, z), 0.f);
    r.w = fmaxf(__fdiv_rn(acc.w, z), 0.f);
    *((float4*)(g_out + (size_t)e*NNODES*CDIM + (size_t)d*128) + lane) = r;
}

// ------------------------- semantic attention (fp64 reduce) -------------------------
__global__ void semscore_kernel(const float* __restrict__ q_l){
    __shared__ double redbuf[128];
    __shared__ double sp[4];
    int t = threadIdx.x;   // 128
    double qv = (double)q_l[t];
    for (int p=0;p<4;p++){
        redbuf[t] = qv * g_colsumd[p*128 + t];
        __syncthreads();
        for (int s=64; s>0; s>>=1){
            if (t < s) redbuf[t] += redbuf[t+s];
            __syncthreads();
        }
        if (t == 0) sp[p] = redbuf[0] * (1.0/(double)NNODES);
        __syncthreads();
    }
    if (t == 0){
        double a0 = sp[0], a1 = sp[2];
        double mx = fmax(a0,a1);
        double e0 = exp(a0-mx), e1 = exp(a1-mx);
        g_attnd[0] = e0/(e0+e1); g_attnd[1] = e1/(e0+e1);
        a0 = sp[1]; a1 = sp[3];
        mx = fmax(a0,a1);
        e0 = exp(a0-mx); e1 = exp(a1-mx);
        g_attnd[2] = e0/(e0+e1); g_attnd[3] = e1/(e0+e1);
    }
}

// ------------------------- combine (g_out already relu'd) -------------------------
__global__ void combine_kernel(){
    int t = blockIdx.y;
    float a0 = (float)g_attnd[t*2], a1 = (float)g_attnd[t*2+1];
    int idx = blockIdx.x*256 + threadIdx.x;
    const int n4 = NNODES*CDIM/4;
    if (idx >= n4) return;
    int pa = (t==0) ? 0 : 1;
    int pb = (t==0) ? 2 : 3;
    float4 va = ((const float4*)(g_out + (size_t)pa*NNODES*CDIM))[idx];
    float4 vb = ((const float4*)(g_out + (size_t)pb*NNODES*CDIM))[idx];
    float4 r;
    r.x = fmaxf(__fadd_rn(__fmul_rn(a0,va.x), __fmul_rn(a1,vb.x)), 0.f);
    r.y = fmaxf(__fadd_rn(__fmul_rn(a0,va.y), __fmul_rn(a1,vb.y)), 0.f);
    r.z = fmaxf(__fadd_rn(__fmul_rn(a0,va.z), __fmul_rn(a1,vb.z)), 0.f);
    r.w = fmaxf(__fadd_rn(__fmul_rn(a0,va.w), __fmul_rn(a1,vb.w)), 0.f);
    ((float4*)(g_xs + (size_t)t*NNODES*CDIM))[idx] = r;
}

// ---------- pooling: serial fp32 in node order per (graph, column) ----------
__global__ void pool_kernel(const int* __restrict__ b0, const int* __restrict__ b1){
    int b = blockIdx.x, t = blockIdx.y;
    const int* batch = t ? b1 : b0;
    int lo, hi;
    {
        int l=0, r=NNODES;
        while (l<r){ int m=(l+r)>>1; if (batch[m] < b) l=m+1; else r=m; }
        lo = l;
        l=0; r=NNODES;
        while (l<r){ int m=(l+r)>>1; if (batch[m] < b+1) l=m+1; else r=m; }
        hi = l;
    }
    int c = threadIdx.x;
    const float* x = g_xs + (size_t)t*NNODES*CDIM;
    float mx = negInf(), sm = 0.f;
    for (int n=lo; n<hi; n++){
        float v = x[(size_t)n*128 + c];
        mx = fmaxf(mx, v);
        sm = __fadd_rn(sm, v);
    }
    if (hi == lo) mx = 0.f;
    int cnt = hi - lo;
    float mean = __fdiv_rn(sm, (float)(cnt > 0 ? cnt : 1));
    g_featd[b*512 + t*256 + c]        = (double)mx;
    g_featd[b*512 + t*256 + 128 + c]  = (double)mean;
}

// ------------------------- PairNorm (fp64) + MLP (fp32) ---------------------------
__global__ void pairnorm_kernel(){
    __shared__ double rss[BGRAPH];
    int c = threadIdx.x;   // 512 threads
    double col[BGRAPH];
    double s = 0.0;
#pragma unroll
    for (int b=0;b<BGRAPH;b++){ col[b] = g_featd[b*512 + c]; s += col[b]; }
    double mean = s * (1.0/(double)BGRAPH);
#pragma unroll
    for (int b=0;b<BGRAPH;b++){ col[b] -= mean; g_featd[b*512 + c] = col[b]; }
    __syncthreads();
    if (c < BGRAPH){
        double ss = 0.0;
        for (int k=0;k<512;k++){ double v = g_featd[c*512 + k]; ss += v*v; }
        rss[c] = 1.0 / sqrt(1e-6 + ss);
    }
    __syncthreads();
#pragma unroll
    for (int b=0;b<BGRAPH;b++) g_feat[b*512 + c] = (float)(100.0 * col[b] * rss[b]);
}

__global__ void mlp1_kernel(const float* __restrict__ w, const float* __restrict__ bias){
    __shared__ float f[512];
    int b = blockIdx.x, t = threadIdx.x;   // 128
    for (int i=t;i<512;i+=128) f[i] = g_feat[b*512 + i];
    __syncthreads();
    float acc = 0.f;
    for (int k=0;k<512;k++) acc = fmaf(f[k], w[k*128 + t], acc);
    g_t1[b*128 + t] = fmaxf(__fadd_rn(acc, bias[t]), 0.f);
}

__global__ void mlp2_kernel(const float* __restrict__ w, const float* __restrict__ bias){
    __shared__ float f[128];
    int b = blockIdx.x, t = threadIdx.x;   // 64
    f[t]    = g_t1[b*128 + t];
    f[t+64] = g_t1[b*128 + t + 64];
    __syncthreads();
    float acc = 0.f;
    for (int k=0;k<128;k++) acc = fmaf(f[k], w[k*64 + t], acc);
    g_t2[b*64 + t] = fmaxf(__fadd_rn(acc, bias[t]), 0.f);
}

__global__ void mlp3_kernel(const float* __restrict__ w, const float* __restrict__ bias,
                            float* __restrict__ out){
    int t = threadIdx.x;   // 64
    if (t >= 2*BGRAPH) return;
    int b = t >> 1, o = t & 1;
    float acc = 0.f;
    for (int k=0;k<64;k++) acc = fmaf(g_t2[b*64 + k], w[k*2 + o], acc);
    out[b*2 + o] = __fadd_rn(acc, bias[o]);
}

// ------------------------- host driver -------------------------
extern "C" void kernel_launch(void* const* d_in, const int* in_sizes, int n_in,
                              void* d_out, int out_size)
{
    const float* proj_w = (const float*)d_in[2];
    const float* proj_b = (const float*)d_in[3];
    const float* a_src  = (const float*)d_in[4];
    const float* a_dst  = (const float*)d_in[5];
    const float* k_w    = (const float*)d_in[6];
    const float* k_b    = (const float*)d_in[7];
    const float* qv     = (const float*)d_in[8];
    const int* ei_bb = (const int*)d_in[15];
    const int* ei_bd = (const int*)d_in[16];
    const int* ei_db = (const int*)d_in[17];
    const int* ei_dd = (const int*)d_in[18];
    const int* batch_b = (const int*)d_in[19];
    const int* batch_d = (const int*)d_in[20];
    float* out = (float*)d_out;

    const int gemmBlocks = (NNODES + 127) / 128;
    const int eBlocks    = (EEDGES + 255) / 256;
    const int dstBlocks  = (NNODES + 7) / 8;
    const int nBlocks256 = (NNODES + 255) / 256;
    const int n4Blocks   = (NNODES*CDIM/4 + 255) / 256;

    load_input_kernel<<<n4Blocks, 256>>>((const float*)d_in[0], (const float*)d_in[1]);

    // CSR build with edge-order rows
    csr_zero_kernel<<<(4*NNODES + 255)/256, 256>>>();
    csr_count_kernel<<<dim3(eBlocks,4), 256>>>(ei_bb, ei_bd, ei_db, ei_dd);
    csr_scan_kernel<<<4, 1024>>>();
    csr_scatter_kernel<<<dim3(eBlocks,4), 256>>>(ei_bb, ei_bd, ei_db, ei_dd);
    row_sort_kernel<<<dim3(nBlocks256,4), 256>>>(ei_bb, ei_bd, ei_db, ei_dd);

    for (int l=0; l<3; l++){
        colsum_zero_kernel<<<1, 512>>>();

        gemm128_kernel<<<dim3(gemmBlocks,2), 256>>>(
            proj_w + (size_t)l*2*CDIM*CDIM, CDIM*CDIM,
            proj_b + (size_t)l*2*CDIM,      CDIM, 0);

        alin2_kernel<<<dim3((NNODES+31)/32, 2), 256>>>(
            a_src + (size_t)l*4*CDIM, a_dst + (size_t)l*4*CDIM);

        dst_attn_kernel<<<dim3(dstBlocks,4), 256>>>();

        gemm128_kernel<<<dim3(gemmBlocks,4), 256>>>(
            k_w + (size_t)l*CDIM*CDIM, 0,
            k_b + (size_t)l*CDIM,      0, 1);
        semscore_kernel<<<1, 128>>>(qv + (size_t)l*CDIM);

        combine_kernel<<<dim3(n4Blocks,2), 256>>>();
    }

    pool_kernel<<<dim3(BGRAPH,2), 128>>>(batch_b, batch_d);

    pairnorm_kernel<<<1, 512>>>();
    mlp1_kernel<<<BGRAPH, 128>>>((const float*)d_in[9],  (const float*)d_in[10]);
    mlp2_kernel<<<BGRAPH, 64>>>((const float*)d_in[11], (const float*)d_in[12]);
    mlp3_kernel<<<1, 64>>>((const float*)d_in[13], (const float*)d_in[14], out);

    (void)in_sizes; (void)n_in; (void)out_size;
}